// round 4
// baseline (speedup 1.0000x reference)
#include <cuda_runtime.h>
#include <cstdint>

// Problem constants
#define B_    64
#define T_    1024
#define D_    300
#define H_    512
#define G_    (4*H_)     // 2048 gate columns
#define KTOT  (D_ + H_)  // 812
#define K2TOT (KTOT/2)   // 406 k-pairs
#define NCTA  128        // each CTA owns 4 h-cols -> 16 gate cols
#define NTHR  256
#define HC    4
#define GC    16
#define PSTRIDE 516      // panel row stride in floats (512 + 4 pad)

// Scratch (no cudaMalloc allowed)
__device__ float    g_h[2][B_ * H_];     // row-major [b][hcol], double-buffered
__device__ float    g_acc[B_];           // dense-layer partials
__device__ unsigned g_bar_count = 0;
__device__ unsigned g_bar_gen   = 0;

// ---- packed fp32 helpers (FFMA2: 2x fp32 FMA throughput, PTX-only) ----
__device__ __forceinline__ void ffma2(uint64_t& d, uint64_t a, uint64_t b) {
    asm volatile("fma.rn.f32x2 %0, %1, %2, %0;" : "+l"(d) : "l"(a), "l"(b));
}
__device__ __forceinline__ uint64_t pack2(float x, float y) {
    uint64_t r; asm("mov.b64 %0, {%1, %2};" : "=l"(r) : "f"(x), "f"(y)); return r;
}
__device__ __forceinline__ float2 unpack2(uint64_t v) {
    float2 f; asm("mov.b64 {%0, %1}, %2;" : "=f"(f.x), "=f"(f.y) : "l"(v)); return f;
}
__device__ __forceinline__ void lds_v2u64(uint64_t& a, uint64_t& b, unsigned addr) {
    asm volatile("ld.shared.v2.u64 {%0, %1}, [%2];" : "=l"(a), "=l"(b) : "r"(addr));
}
// ---- cp.async (L1-bypassing 16B global->shared, register-free) ----
__device__ __forceinline__ void cp_async16(unsigned dst, const void* src) {
    asm volatile("cp.async.cg.shared.global [%0], [%1], 16;" :: "r"(dst), "l"(src));
}
__device__ __forceinline__ void cp_async_commit() {
    asm volatile("cp.async.commit_group;" ::: "memory");
}
__device__ __forceinline__ void cp_async_wait_all() {
    asm volatile("cp.async.wait_group 0;" ::: "memory");
}
// ---- scoped atomics for the grid barrier ----
__device__ __forceinline__ unsigned atom_add_acqrel_gpu(unsigned* p, unsigned v) {
    unsigned r;
    asm volatile("atom.acq_rel.gpu.global.add.u32 %0, [%1], %2;"
                 : "=r"(r) : "l"(p), "r"(v) : "memory");
    return r;
}
__device__ __forceinline__ void atom_add_release_gpu(unsigned* p, unsigned v) {
    unsigned r;
    asm volatile("atom.release.gpu.global.add.u32 %0, [%1], %2;"
                 : "=r"(r) : "l"(p), "r"(v) : "memory");
}
__device__ __forceinline__ unsigned ld_acquire_gpu(const unsigned* p) {
    unsigned r;
    asm volatile("ld.acquire.gpu.global.u32 %0, [%1];" : "=r"(r) : "l"(p) : "memory");
    return r;
}
__device__ __forceinline__ void st_relaxed_gpu(unsigned* p, unsigned v) {
    asm volatile("st.relaxed.gpu.global.u32 [%0], %1;" :: "l"(p), "r"(v) : "memory");
}
__device__ __forceinline__ float sigm(float x)  { return 1.0f / (1.0f + __expf(-x)); }
__device__ __forceinline__ float tanh_f(float x){ return 2.0f * sigm(2.0f * x) - 1.0f; }

// W SMEM layout: Wsm[k2][c*2 + half] = W_lstm[2*k2 + half][col(c)]
// -> LDS.128 at (k2*64B... actually k2*128B + q0*8B) yields the (even,odd) w-pairs
//    for cols q0 and q0+1 as two u64 f32x2 operands. No operand packing needed.
extern __shared__ float smem_dyn[];
__global__ void __launch_bounds__(NTHR, 1)
lstm_scan_kernel(const float* __restrict__ essays,
                 const float* __restrict__ W_lstm,
                 const float* __restrict__ b_lstm,
                 const float* __restrict__ W_dense)
{
    float* Wsm  = smem_dyn;                 // [K2TOT][32]  = 51,968 B
    float* Apan = smem_dyn + K2TOT*32;      // [64][PSTRIDE] = 132,096 B

    const int tid  = threadIdx.x;
    const int cc   = blockIdx.x;
    const int w    = tid >> 5;
    const int lane = tid & 31;
    const int m    = w*8 + (lane & 7);   // batch row
    const int ng   = lane >> 3;          // gate 0..3
    const int q0   = ng*4;               // first of this thread's 4 local cols

    // Load W slice into pair-major layout
    for (int idx = tid; idx < KTOT*GC; idx += NTHR) {
        int k = idx >> 4, c = idx & 15;
        int col = (c >> 2) * H_ + cc*HC + (c & 3);
        Wsm[((k >> 1)*GC + c)*2 + (k & 1)] = W_lstm[(size_t)k * G_ + col];
    }

    const int colb = ng*H_ + cc*HC;
    const uint64_t bias0 = pack2(b_lstm[colb+0], 0.0f);
    const uint64_t bias1 = pack2(b_lstm[colb+1], 0.0f);
    const uint64_t bias2 = pack2(b_lstm[colb+2], 0.0f);
    const uint64_t bias3 = pack2(b_lstm[colb+3], 0.0f);

    const int hcol = cc*HC + ng;
    g_h[0][m*H_ + hcol] = 0.0f;                 // h_{-1} = 0
    if (cc == 0 && tid < B_) g_acc[tid] = 0.0f;

    const unsigned wbase = (unsigned)__cvta_generic_to_shared(Wsm);
    const unsigned abase = (unsigned)__cvta_generic_to_shared(Apan);

    __shared__ unsigned s_gen;
    if (tid == 0) s_gen = ld_acquire_gpu(&g_bar_gen);
    __syncthreads();
    const unsigned base = s_gen;

    // arrive #0 (zero-init published via release chain)
    if (tid == 0) {
        unsigned a = atom_add_acqrel_gpu(&g_bar_count, 1);
        if (a == NCTA-1) {
            st_relaxed_gpu(&g_bar_count, 0);
            atom_add_release_gpu(&g_bar_gen, 1);
        }
    }

    float c_st = 0.0f, hsum = 0.0f;
    const float* xrow = essays + (size_t)m * (T_ * D_);

    for (int t = 0; t < T_; t++) {
        // ---- wait for h_{t-1} globally visible ----
        const unsigned target = base + (unsigned)(t + 1);
        if (tid == 0) {
            while ((int)(ld_acquire_gpu(&g_bar_gen) - target) < 0) { }
        }
        __syncthreads();

        // ---- kick off async panel staging: g_h -> Apan (L2-direct, no regs) ----
        {
            const float* hb = g_h[t & 1];
            #pragma unroll
            for (int r = 0; r < 32; r++) {
                int idx = tid + r*NTHR;        // 8192 16B chunks
                int mm = idx >> 7, kk = (idx & 127) << 2;
                cp_async16(abase + (unsigned)(mm*PSTRIDE + kk)*4u,
                           hb + (size_t)mm*H_ + kk);
            }
            cp_async_commit();
        }

        uint64_t acc0 = bias0, acc1 = bias1, acc2 = bias2, acc3 = bias3;

        // ---- X-phase (overlaps cp.async flight): gates += x_t @ Wx ----
        {
            const ulonglong2* xp = (const ulonglong2*)(xrow + (size_t)t * D_);
            #pragma unroll 5
            for (int k4 = 0; k4 < D_/4; k4++) {
                ulonglong2 a = xp[k4];              // (x_{4k4},x_{4k4+1}),(x_{4k4+2},x_{4k4+3})
                unsigned wa = wbase + (unsigned)(2*k4)*128u + (unsigned)q0*8u;
                uint64_t w0, w1, w2, w3;
                lds_v2u64(w0, w1, wa);
                lds_v2u64(w2, w3, wa + 16);
                ffma2(acc0, w0, a.x); ffma2(acc1, w1, a.x);
                ffma2(acc2, w2, a.x); ffma2(acc3, w3, a.x);
                lds_v2u64(w0, w1, wa + 128);
                lds_v2u64(w2, w3, wa + 144);
                ffma2(acc0, w0, a.y); ffma2(acc1, w1, a.y);
                ffma2(acc2, w2, a.y); ffma2(acc3, w3, a.y);
            }
        }

        // ---- panel ready ----
        cp_async_wait_all();
        __syncthreads();

        // ---- H-phase: gates += h_{t-1} @ Wh over 512 k straight ----
        {
            const float* arow = &Apan[m*PSTRIDE];
            #pragma unroll 8
            for (int k4 = 0; k4 < H_/4; k4++) {
                ulonglong2 a = *(const ulonglong2*)(arow + k4*4);
                unsigned wa = wbase + (unsigned)(D_/2 + 2*k4)*128u + (unsigned)q0*8u;
                uint64_t w0, w1, w2, w3;
                lds_v2u64(w0, w1, wa);
                lds_v2u64(w2, w3, wa + 16);
                ffma2(acc0, w0, a.x); ffma2(acc1, w1, a.x);
                ffma2(acc2, w2, a.x); ffma2(acc3, w3, a.x);
                lds_v2u64(w0, w1, wa + 128);
                lds_v2u64(w2, w3, wa + 144);
                ffma2(acc0, w0, a.y); ffma2(acc1, w1, a.y);
                ffma2(acc2, w2, a.y); ffma2(acc3, w3, a.y);
            }
        }
        __syncthreads();   // H-reads of Apan done before exchange overwrites it

        // ---- gate exchange: thread owns (gate ng, cols q0..q0+3); needs (gates 0..3, col ng)
        float2 v0 = unpack2(acc0), v1 = unpack2(acc1), v2 = unpack2(acc2), v3 = unpack2(acc3);
        Apan[(q0+0)*65 + m] = v0.x + v0.y;
        Apan[(q0+1)*65 + m] = v1.x + v1.y;
        Apan[(q0+2)*65 + m] = v2.x + v2.y;
        Apan[(q0+3)*65 + m] = v3.x + v3.y;
        __syncthreads();
        float gi = Apan[(0*4 + ng)*65 + m];
        float gj = Apan[(1*4 + ng)*65 + m];
        float gf = Apan[(2*4 + ng)*65 + m];
        float go = Apan[(3*4 + ng)*65 + m];

        float nc = c_st * sigm(gf + 1.0f) + sigm(gi) * tanh_f(gj);
        float nh = tanh_f(nc) * sigm(go);
        c_st = nc;
        hsum += nh;
        g_h[(t+1) & 1][m*H_ + hcol] = nh;

        __syncthreads();   // all threads' h stores program-ordered before tid0's release

        if (t < T_ - 1) {
            if (tid == 0) {
                unsigned a = atom_add_acqrel_gpu(&g_bar_count, 1);
                if (a == NCTA-1) {
                    st_relaxed_gpu(&g_bar_count, 0);
                    atom_add_release_gpu(&g_bar_gen, 1);
                }
            }
        }
    }

    // Dense-layer partial: mean(h)[m][hcol] * W_dense[hcol]; reduce 4 ng lanes; atomicAdd
    float part = hsum * (1.0f / (float)T_) * W_dense[hcol];
    part += __shfl_xor_sync(0xffffffffu, part, 8);
    part += __shfl_xor_sync(0xffffffffu, part, 16);
    if (lane < 8) atomicAdd(&g_acc[m], part);
}

__global__ void finalize_kernel(const float* __restrict__ b_dense,
                                float* __restrict__ out)
{
    int b = threadIdx.x;  // 64 threads
    out[b] = 1.0f / (1.0f + expf(-(g_acc[b] + b_dense[0])));
}

extern "C" void kernel_launch(void* const* d_in, const int* in_sizes, int n_in,
                              void* d_out, int out_size)
{
    const float* essays  = (const float*)d_in[0];
    const float* W_lstm  = (const float*)d_in[1];
    const float* b_lstm  = (const float*)d_in[2];
    const float* W_dense = (const float*)d_in[3];
    const float* b_dense = (const float*)d_in[4];
    float* out = (float*)d_out;

    const int smem_bytes = (K2TOT*32 + B_*PSTRIDE) * (int)sizeof(float); // 51968+132096=184064
    cudaFuncSetAttribute(lstm_scan_kernel,
                         cudaFuncAttributeMaxDynamicSharedMemorySize, smem_bytes);

    lstm_scan_kernel<<<NCTA, NTHR, smem_bytes>>>(essays, W_lstm, b_lstm, W_dense);
    finalize_kernel<<<1, B_>>>(b_dense, out);
}